// round 7
// baseline (speedup 1.0000x reference)
#include <cuda_runtime.h>
#include <cuda_bf16.h>

#define BB 64
#define VV 64
#define TT 256
#define FF 64
#define NT  256
#define BPB 32    // batches per block -> grid = 256*2 = 512 = ONE wave at 4 CTA/SM
#define AP  68    // adj row pitch: 272B, 16B-aligned, conflict-free LDS.128 (68 mod 32 = 4)

// ---------------------------------------------------------------------------
// Fused single-wave kernel. Block = (t, bc): one timestep, 32 batches.
//  Phase 1: adj = sigmoid(A_t)*(1-I)+I (smem); xs[bl][w] = X[b,w,t];
//           hs[bl][v] = sum_w adj[v][w]*xs[bl][w]  (reg-blocked, LDS.128)
//  Phase 2: 32 x 16KB coalesced float4 streaming stores.
// All 512 blocks resident at once -> phase-1 cost paid once chip-wide.
// ---------------------------------------------------------------------------
__global__ __launch_bounds__(NT)
void gnn_fused(const float* __restrict__ X,
               const float* __restrict__ A,
               const float* __restrict__ W,
               float* __restrict__ out)
{
    __shared__ float adj[VV][AP];       // 17.4 KB
    __shared__ float xs[BPB][VV];       // 8 KB
    __shared__ float hs[BPB][VV];       // 8 KB

    const int t   = blockIdx.x;         // 0..255
    const int bc  = blockIdx.y;         // 0..1
    const int tid = threadIdx.x;
    const int b0  = bc * BPB;

    // ---- adj = sigmoid(A_t) off-diag, 1 on diag (2x redundant per t only) ----
    const float* At = A + (size_t)t * VV * VV;
    #pragma unroll
    for (int k = 0; k < (VV * VV) / NT; ++k) {       // 16 iters, coalesced
        int i = tid + k * NT;
        int v = i >> 6, w = i & 63;
        float a = At[i];
        float s = 1.0f / (1.0f + __expf(-a));
        adj[v][w] = (v == w) ? 1.0f : s;             // consecutive banks: conflict-free
    }

    // ---- stage xs[bl][w] = X[b0+bl, w, t] ----
    #pragma unroll
    for (int k = 0; k < (BPB * VV) / NT; ++k) {      // 8 iters
        int i  = tid + k * NT;
        int bl = i >> 6, w = i & 63;
        xs[bl][w] = X[((size_t)(b0 + bl) * VV + w) * TT + t];
    }
    __syncthreads();

    // ---- dot: thread owns v=tid&31 (and v+32) for 4 bl values; adj rows
    //      loaded once per w4 and reused across the 4 bl (8 accumulators) ----
    {
        const int v  = tid & 31;
        const int bw = tid >> 5;        // 0..7; bl = bw + 8*j
        float s0[4] = {0.f, 0.f, 0.f, 0.f};
        float s1[4] = {0.f, 0.f, 0.f, 0.f};
        #pragma unroll
        for (int w4 = 0; w4 < 16; ++w4) {
            float4 p = *reinterpret_cast<const float4*>(&adj[v     ][w4 * 4]);  // conflict-free
            float4 q = *reinterpret_cast<const float4*>(&adj[v + 32][w4 * 4]);  // conflict-free
            #pragma unroll
            for (int j = 0; j < 4; ++j) {
                float4 x = *reinterpret_cast<const float4*>(&xs[bw + 8 * j][w4 * 4]); // warp bcast
                s0[j] = fmaf(p.x, x.x, s0[j]); s0[j] = fmaf(p.y, x.y, s0[j]);
                s0[j] = fmaf(p.z, x.z, s0[j]); s0[j] = fmaf(p.w, x.w, s0[j]);
                s1[j] = fmaf(q.x, x.x, s1[j]); s1[j] = fmaf(q.y, x.y, s1[j]);
                s1[j] = fmaf(q.z, x.z, s1[j]); s1[j] = fmaf(q.w, x.w, s1[j]);
            }
        }
        #pragma unroll
        for (int j = 0; j < 4; ++j) {
            hs[bw + 8 * j][v]      = s0[j];
            hs[bw + 8 * j][v + 32] = s1[j];
        }
    }

    // f index loop-invariant per thread -> hoist W vector
    const float4 wv = reinterpret_cast<const float4*>(W)[tid & 15];
    __syncthreads();

    // ---- expansion: 32 rows x 16 KB, float4 streaming stores ----
    #pragma unroll 4
    for (int bl = 0; bl < BPB; ++bl) {
        float4* o = reinterpret_cast<float4*>(
            out + ((size_t)(b0 + bl) * TT + t) * (VV * FF));
        #pragma unroll
        for (int j = 0; j < (VV * FF / 4) / NT; ++j) {   // 4 iters
            int p = j * NT + tid;                        // float4 idx, coalesced
            float h = hs[bl][p >> 4];
            float4 r;
            r.x = h * wv.x; r.y = h * wv.y; r.z = h * wv.z; r.w = h * wv.w;
            r.x = (r.x >= 0.0f) ? r.x : 0.01f * r.x;
            r.y = (r.y >= 0.0f) ? r.y : 0.01f * r.y;
            r.z = (r.z >= 0.0f) ? r.z : 0.01f * r.z;
            r.w = (r.w >= 0.0f) ? r.w : 0.01f * r.w;
            __stcs(&o[p], r);                            // evict-first stream
        }
    }
}

extern "C" void kernel_launch(void* const* d_in, const int* in_sizes, int n_in,
                              void* d_out, int out_size) {
    const float* X = (const float*)d_in[0];   // [64, 64, 256]
    const float* A = (const float*)d_in[1];   // [256, 64, 64]
    const float* W = (const float*)d_in[2];   // [64, 1]
    float* out = (float*)d_out;               // [64, 256, 4096]
    (void)in_sizes; (void)n_in; (void)out_size;

    dim3 grid(TT, BB / BPB);                  // (256, 2) = 512 blocks, one wave
    gnn_fused<<<grid, NT>>>(X, A, W, out);
}

// round 8
// speedup vs baseline: 1.1692x; 1.1692x over previous
#include <cuda_runtime.h>
#include <cuda_bf16.h>

#define BB 64
#define VV 64
#define TT 256
#define FF 64
#define NT  256
#define BPB 16    // batches per block -> grid (256,4) = 1024 blocks
#define AP  68    // adj row pitch: 272B, 16B-aligned; LDS.128 conflict-free (68 mod 32 = 4)

// ---------------------------------------------------------------------------
// Fused kernel, tuned for resident-warp count: 6 CTAs/SM (forced), 48 warps/SM,
// ~1.15 waves. Block = (t, bc): one timestep, 16 batches.
//  Phase 1: adj = sigmoid(A_t)*(1-I)+I (vectorized LDG.128/STS.128);
//           xs[bl][w] = X[b,w,t];  hs = adj @ xs  (LDS.128 reg-blocked dot)
//  Phase 2: 16 x 16KB coalesced float4 streaming stores (64 per thread).
// ---------------------------------------------------------------------------
__global__ __launch_bounds__(NT, 6)
void gnn_fused(const float* __restrict__ X,
               const float* __restrict__ A,
               const float* __restrict__ W,
               float* __restrict__ out)
{
    __shared__ float adj[VV][AP];       // 17.4 KB
    __shared__ float xs[BPB][VV];       // 4 KB
    __shared__ float hs[BPB][VV];       // 4 KB

    const int t   = blockIdx.x;         // 0..255
    const int bc  = blockIdx.y;         // 0..3
    const int tid = threadIdx.x;
    const int b0  = bc * BPB;

    // ---- adj = sigmoid(A_t) off-diag, 1 on diag; vectorized 4x f4/thread ----
    const float4* Ag = reinterpret_cast<const float4*>(A + (size_t)t * VV * VV);
    #pragma unroll
    for (int k = 0; k < 4; ++k) {
        int i  = tid + k * NT;          // float4 index 0..1023, coalesced
        int v  = i >> 4;
        int w4 = i & 15;
        float4 a = Ag[i];
        float4 s;
        s.x = 1.0f / (1.0f + __expf(-a.x));
        s.y = 1.0f / (1.0f + __expf(-a.y));
        s.z = 1.0f / (1.0f + __expf(-a.z));
        s.w = 1.0f / (1.0f + __expf(-a.w));
        int wbase = w4 * 4;             // diagonal fixup: v in [wbase, wbase+3]?
        if (v == wbase + 0) s.x = 1.0f;
        if (v == wbase + 1) s.y = 1.0f;
        if (v == wbase + 2) s.z = 1.0f;
        if (v == wbase + 3) s.w = 1.0f;
        *reinterpret_cast<float4*>(&adj[v][wbase]) = s;
    }

    // ---- stage xs[bl][w] = X[b0+bl, w, t] ----
    #pragma unroll
    for (int k = 0; k < (BPB * VV) / NT; ++k) {      // 4 iters
        int i  = tid + k * NT;
        int bl = i >> 6, w = i & 63;
        xs[bl][w] = X[((size_t)(b0 + bl) * VV + w) * TT + t];
    }
    __syncthreads();

    // ---- dot: thread owns v=tid&31 and v+32, for bl = bw and bw+8 ----
    {
        const int v  = tid & 31;
        const int bw = tid >> 5;        // 0..7
        float s00 = 0.f, s01 = 0.f, s10 = 0.f, s11 = 0.f;
        #pragma unroll
        for (int w4 = 0; w4 < 16; ++w4) {
            float4 p  = *reinterpret_cast<const float4*>(&adj[v     ][w4 * 4]); // conflict-free
            float4 q  = *reinterpret_cast<const float4*>(&adj[v + 32][w4 * 4]); // conflict-free
            float4 x0 = *reinterpret_cast<const float4*>(&xs[bw    ][w4 * 4]);  // warp bcast
            float4 x1 = *reinterpret_cast<const float4*>(&xs[bw + 8][w4 * 4]);  // warp bcast
            s00 = fmaf(p.x, x0.x, s00); s00 = fmaf(p.y, x0.y, s00);
            s00 = fmaf(p.z, x0.z, s00); s00 = fmaf(p.w, x0.w, s00);
            s01 = fmaf(q.x, x0.x, s01); s01 = fmaf(q.y, x0.y, s01);
            s01 = fmaf(q.z, x0.z, s01); s01 = fmaf(q.w, x0.w, s01);
            s10 = fmaf(p.x, x1.x, s10); s10 = fmaf(p.y, x1.y, s10);
            s10 = fmaf(p.z, x1.z, s10); s10 = fmaf(p.w, x1.w, s10);
            s11 = fmaf(q.x, x1.x, s11); s11 = fmaf(q.y, x1.y, s11);
            s11 = fmaf(q.z, x1.z, s11); s11 = fmaf(q.w, x1.w, s11);
        }
        hs[bw    ][v]      = s00;
        hs[bw    ][v + 32] = s01;
        hs[bw + 8][v]      = s10;
        hs[bw + 8][v + 32] = s11;
    }

    // f index loop-invariant per thread -> hoist W vector
    const float4 wv = reinterpret_cast<const float4*>(W)[tid & 15];
    __syncthreads();

    // ---- expansion: 16 rows x 16 KB, float4 streaming stores ----
    #pragma unroll 4
    for (int bl = 0; bl < BPB; ++bl) {
        float4* o = reinterpret_cast<float4*>(
            out + ((size_t)(b0 + bl) * TT + t) * (VV * FF));
        #pragma unroll
        for (int j = 0; j < (VV * FF / 4) / NT; ++j) {   // 4 iters
            int p = j * NT + tid;                        // float4 idx, coalesced
            float h = hs[bl][p >> 4];
            float4 r;
            r.x = h * wv.x; r.y = h * wv.y; r.z = h * wv.z; r.w = h * wv.w;
            r.x = (r.x >= 0.0f) ? r.x : 0.01f * r.x;
            r.y = (r.y >= 0.0f) ? r.y : 0.01f * r.y;
            r.z = (r.z >= 0.0f) ? r.z : 0.01f * r.z;
            r.w = (r.w >= 0.0f) ? r.w : 0.01f * r.w;
            __stcs(&o[p], r);                            // evict-first stream
        }
    }
}

extern "C" void kernel_launch(void* const* d_in, const int* in_sizes, int n_in,
                              void* d_out, int out_size) {
    const float* X = (const float*)d_in[0];   // [64, 64, 256]
    const float* A = (const float*)d_in[1];   // [256, 64, 64]
    const float* W = (const float*)d_in[2];   // [64, 1]
    float* out = (float*)d_out;               // [64, 256, 4096]
    (void)in_sizes; (void)n_in; (void)out_size;

    dim3 grid(TT, BB / BPB);                  // (256, 4) = 1024 blocks
    gnn_fused<<<grid, NT>>>(X, A, W, out);
}

// round 9
// speedup vs baseline: 1.2690x; 1.0854x over previous
#include <cuda_runtime.h>
#include <cuda_bf16.h>

#define BB 64
#define VV 64
#define TT 256
#define FF 64
#define NT  256
#define BPB 8     // one warp per batch row
#define AP  68    // adj row pitch: 272B, 16B-aligned; LDS.128 conflict-free (68 mod 32 = 4)

// ---------------------------------------------------------------------------
// Fused kernel, warp-owned rows. Block = (t, bc): one timestep, 8 batches.
//  Stage:  adj = sigmoid(A_t)*(1-I)+I (LDG.128/STS.128); xs[bl][w] = X[b,w,t]
//  ONE __syncthreads. Then warp wid independently:
//    dot:   hs[wid][v] = sum_w adj[v][w]*xs[wid][w]   (LDS.128, 2 dots/lane)
//    store: out[b0+wid, t, :] row (16 KB) as float4 __stcs  (no block barrier)
//  Warps de-stagger -> store stream stays busy through other warps' dots.
// ---------------------------------------------------------------------------
__global__ __launch_bounds__(NT)
void gnn_fused(const float* __restrict__ X,
               const float* __restrict__ A,
               const float* __restrict__ W,
               float* __restrict__ out)
{
    __shared__ float adj[VV][AP];       // 17.4 KB
    __shared__ float xs[BPB][VV];       // 2 KB
    __shared__ float hs[BPB][VV];       // 2 KB

    const int t   = blockIdx.x;         // 0..255
    const int bc  = blockIdx.y;         // 0..7
    const int tid = threadIdx.x;
    const int wid = tid >> 5;           // 0..7 == bl
    const int lid = tid & 31;
    const int b0  = bc * BPB;

    // ---- adj = sigmoid(A_t) off-diag, 1 on diag; 4x float4 per thread ----
    const float4* Ag = reinterpret_cast<const float4*>(A + (size_t)t * VV * VV);
    #pragma unroll
    for (int k = 0; k < 4; ++k) {
        int i  = tid + k * NT;          // float4 index 0..1023, coalesced
        int v  = i >> 4;
        int w4 = i & 15;
        float4 a = Ag[i];
        float4 s;
        s.x = 1.0f / (1.0f + __expf(-a.x));
        s.y = 1.0f / (1.0f + __expf(-a.y));
        s.z = 1.0f / (1.0f + __expf(-a.z));
        s.w = 1.0f / (1.0f + __expf(-a.w));
        int wbase = w4 * 4;
        if (v == wbase + 0) s.x = 1.0f;
        if (v == wbase + 1) s.y = 1.0f;
        if (v == wbase + 2) s.z = 1.0f;
        if (v == wbase + 3) s.w = 1.0f;
        *reinterpret_cast<float4*>(&adj[v][wbase]) = s;
    }

    // ---- stage xs[bl][w] = X[b0+bl, w, t] ----
    #pragma unroll
    for (int k = 0; k < (BPB * VV) / NT; ++k) {      // 2 iters
        int i  = tid + k * NT;
        int bl = i >> 6, w = i & 63;
        xs[bl][w] = X[((size_t)(b0 + bl) * VV + w) * TT + t];
    }

    // f index per lane is invariant: p mod 16 == lid mod 16
    const float4 wv = reinterpret_cast<const float4*>(W)[lid & 15];

    __syncthreads();                    // ONLY block-wide barrier

    // ---- warp-private dot: lane owns v=lid and v+32 of row bl=wid ----
    {
        float s0 = 0.f, s1 = 0.f;
        #pragma unroll
        for (int w4 = 0; w4 < 16; ++w4) {
            float4 p = *reinterpret_cast<const float4*>(&adj[lid     ][w4 * 4]); // conflict-free
            float4 q = *reinterpret_cast<const float4*>(&adj[lid + 32][w4 * 4]); // conflict-free
            float4 x = *reinterpret_cast<const float4*>(&xs[wid][w4 * 4]);       // warp bcast
            s0 = fmaf(p.x, x.x, s0); s0 = fmaf(p.y, x.y, s0);
            s0 = fmaf(p.z, x.z, s0); s0 = fmaf(p.w, x.w, s0);
            s1 = fmaf(q.x, x.x, s1); s1 = fmaf(q.y, x.y, s1);
            s1 = fmaf(q.z, x.z, s1); s1 = fmaf(q.w, x.w, s1);
        }
        hs[wid][lid]      = s0;
        hs[wid][lid + 32] = s1;
    }
    __syncwarp();                       // warp-local: hs[wid] visible to own warp

    // ---- warp streams its own 16 KB row; no block barrier -> de-staggered ----
    float4* o = reinterpret_cast<float4*>(
        out + ((size_t)(b0 + wid) * TT + t) * (VV * FF));
    #pragma unroll 8
    for (int j = 0; j < (VV * FF / 4) / 32; ++j) {   // 32 iters
        int p = j * 32 + lid;                        // float4 idx, coalesced per warp
        float h = hs[wid][p >> 4];                   // 2 distinct addrs/warp: bcast
        float4 r;
        r.x = h * wv.x; r.y = h * wv.y; r.z = h * wv.z; r.w = h * wv.w;
        r.x = fmaxf(r.x, 0.01f * r.x);               // leaky: max(x, .01x) both signs
        r.y = fmaxf(r.y, 0.01f * r.y);
        r.z = fmaxf(r.z, 0.01f * r.z);
        r.w = fmaxf(r.w, 0.01f * r.w);
        __stcs(&o[p], r);                            // evict-first stream
    }
}

extern "C" void kernel_launch(void* const* d_in, const int* in_sizes, int n_in,
                              void* d_out, int out_size) {
    const float* X = (const float*)d_in[0];   // [64, 64, 256]
    const float* A = (const float*)d_in[1];   // [256, 64, 64]
    const float* W = (const float*)d_in[2];   // [64, 1]
    float* out = (float*)d_out;               // [64, 256, 4096]
    (void)in_sizes; (void)n_in; (void)out_size;

    dim3 grid(TT, BB / BPB);                  // (256, 8) = 2048 blocks
    gnn_fused<<<grid, NT>>>(X, A, W, out);
}